// round 2
// baseline (speedup 1.0000x reference)
#include <cuda_runtime.h>
#include <math_constants.h>

// Tiny transformer, fully fused into ONE kernel / ONE block.
// CONTEXT=5, DIM=32, HEADS=4 (hd=8), NTOK=13, LAYERS=4.
// All weights are staged into dynamic shared memory ONCE at kernel entry
// (single overlapped global round-trip), so the serial per-layer dependency
// chain only ever touches shared memory (29-cyc latency) after that.

#define CTX    5
#define DIM    32
#define NTOK   13
#define HEADS  4
#define HD     8
#define LAYERS 4

#define WELEM  (LAYERS * DIM * DIM)       // 4096 floats per weight tensor
#define W6     (6 * WELEM)                // wq|wk|wv|wp|w1|w2
#define B3     (3 * LAYERS * DIM)         // bp|b1|b2
#define WUELEM (DIM * NTOK)               // 416
#define NACT   (6 * CTX * DIM + HEADS * CTX * CTX)   // X,Q,K,V,Yp,H + S

#define SMEM_FLOATS (W6 + B3 + WUELEM + NTOK + NACT)
#define SMEM_BYTES  (SMEM_FLOATS * 4)

__global__ __launch_bounds__(160, 1)
void transformer_fused_kernel(
    const int*   __restrict__ toks,      // [5]
    const float* __restrict__ pos,       // [5,32]
    const float* __restrict__ tokemb,    // [13,32]
    const float* __restrict__ gWq,       // [4,32,32]
    const float* __restrict__ gWk,
    const float* __restrict__ gWv,
    const float* __restrict__ gWp,
    const float* __restrict__ gbp,       // [4,32]
    const float* __restrict__ gW1,
    const float* __restrict__ gb1,
    const float* __restrict__ gW2,
    const float* __restrict__ gb2,
    const float* __restrict__ gWu,       // [32,13]
    const float* __restrict__ gbu,       // [13]
    float*       __restrict__ out)       // [5,13]
{
    extern __shared__ float sm[];
    // ---- shared layout ----
    float* sW  = sm;                      // 6 weight tensors, contiguous
    float* sB  = sW + W6;                 // bp|b1|b2
    float* sWu = sB + B3;
    float* sbu = sWu + WUELEM;
    float* Xs  = sbu + NTOK;              // [5][32]
    float* Qs  = Xs  + CTX * DIM;
    float* Ks  = Qs  + CTX * DIM;
    float* Vs  = Ks  + CTX * DIM;
    float* Yp  = Vs  + CTX * DIM;
    float* Hs  = Yp  + CTX * DIM;
    float* Ss  = Hs  + CTX * DIM;         // [4][5][5]

    const int tid = threadIdx.x;          // 0..159
    const int c   = tid >> 5;             // warp id == context row
    const int d   = tid & 31;             // lane == feature col

    // ---- Embedding (issued first so its loads overlap the weight staging) ----
    Xs[c * DIM + d] = tokemb[toks[c] * DIM + d] + pos[c * DIM + d];

    // ---- Stage all weights into shared memory (float4, fully parallel) ----
    {
        const float4* src[6] = { (const float4*)gWq, (const float4*)gWk,
                                 (const float4*)gWv, (const float4*)gWp,
                                 (const float4*)gW1, (const float4*)gW2 };
        float4* dst = (float4*)sW;
        #pragma unroll
        for (int t = 0; t < 6; ++t) {
            const float4* s = src[t];
            float4* dd = dst + t * (WELEM / 4);
            for (int j = tid; j < WELEM / 4; j += 160)
                dd[j] = s[j];
        }
        // biases: bp|b1|b2 (3 * 128 floats)
        if (tid < 128) {
            sB[tid]       = gbp[tid];
            sB[128 + tid] = gb1[tid];
            sB[256 + tid] = gb2[tid];
        }
        // Wu (416) + bu (13)
        for (int j = tid; j < WUELEM; j += 160) sWu[j] = gWu[j];
        if (tid < NTOK) sbu[tid] = gbu[tid];
    }
    __syncthreads();

    const float* swq = sW;
    const float* swk = sW + 1 * WELEM;
    const float* swv = sW + 2 * WELEM;
    const float* swp = sW + 3 * WELEM;
    const float* sw1 = sW + 4 * WELEM;
    const float* sw2 = sW + 5 * WELEM;

    #pragma unroll 1
    for (int l = 0; l < LAYERS; ++l) {
        const float* wq = swq + l * DIM * DIM;
        const float* wk = swk + l * DIM * DIM;
        const float* wv = swv + l * DIM * DIM;
        const float* wp = swp + l * DIM * DIM;
        const float* w1 = sw1 + l * DIM * DIM;
        const float* w2 = sw2 + l * DIM * DIM;
        const float* lbp = sB +            l * DIM;
        const float* lb1 = sB + 128 +      l * DIM;
        const float* lb2 = sB + 256 +      l * DIM;

        // ---- Q,K,V = X @ {Wq,Wk,Wv}  (2-way split accumulators) ----
        {
            float q0 = 0.f, q1 = 0.f, k0 = 0.f, k1 = 0.f, v0 = 0.f, v1 = 0.f;
            #pragma unroll
            for (int i = 0; i < DIM; i += 2) {
                const float x0 = Xs[c * DIM + i];
                const float x1 = Xs[c * DIM + i + 1];
                q0 = fmaf(x0, wq[ i      * DIM + d], q0);
                q1 = fmaf(x1, wq[(i + 1) * DIM + d], q1);
                k0 = fmaf(x0, wk[ i      * DIM + d], k0);
                k1 = fmaf(x1, wk[(i + 1) * DIM + d], k1);
                v0 = fmaf(x0, wv[ i      * DIM + d], v0);
                v1 = fmaf(x1, wv[(i + 1) * DIM + d], v1);
            }
            Qs[c * DIM + d] = q0 + q1;
            Ks[c * DIM + d] = k0 + k1;
            Vs[c * DIM + d] = v0 + v1;
        }
        __syncthreads();

        // ---- Scores + softmax, fused: one thread per (h, q) row ----
        if (tid < HEADS * CTX) {              // 20 threads
            const int h  = tid / CTX;
            const int qq = tid % CTX;
            float sc[CTX];
            float m = -CUDART_INF_F;
            for (int kk = 0; kk <= qq; ++kk) {
                float a = 0.f;
                #pragma unroll
                for (int i = 0; i < HD; ++i)
                    a = fmaf(Qs[qq * DIM + h * HD + i],
                             Ks[kk * DIM + h * HD + i], a);
                sc[kk] = a * 0.17677669529663687f;   // 1/sqrt(32)
                m = fmaxf(m, sc[kk]);
            }
            float sum = 0.f;
            for (int kk = 0; kk <= qq; ++kk) {
                sc[kk] = __expf(sc[kk] - m);
                sum += sc[kk];
            }
            const float inv = 1.f / sum;
            float* srow = Ss + (h * CTX + qq) * CTX;
            for (int kk = 0; kk <= qq; ++kk)  srow[kk] = sc[kk] * inv;
            for (int kk = qq + 1; kk < CTX; ++kk) srow[kk] = 0.f;
        }
        __syncthreads();

        // ---- Ycat = S @ V  (reuse Qs as Ycat) ----
        {
            const int h = d >> 3;
            const float* srow = Ss + (h * CTX + c) * CTX;
            float y = 0.f;
            #pragma unroll
            for (int kk = 0; kk < CTX; ++kk)
                y = fmaf(srow[kk], Vs[kk * DIM + d], y);
            Qs[c * DIM + d] = y;
        }
        __syncthreads();

        // ---- Yproj = Ycat @ Wp + bp ----
        {
            float y0 = lbp[d], y1 = 0.f;
            #pragma unroll
            for (int i = 0; i < DIM; i += 2) {
                y0 = fmaf(Qs[c * DIM + i],     wp[ i      * DIM + d], y0);
                y1 = fmaf(Qs[c * DIM + i + 1], wp[(i + 1) * DIM + d], y1);
            }
            Yp[c * DIM + d] = y0 + y1;
        }
        __syncthreads();

        // ---- H = relu(Yproj @ W1 + b1) ----
        {
            float y0 = lb1[d], y1 = 0.f;
            #pragma unroll
            for (int i = 0; i < DIM; i += 2) {
                y0 = fmaf(Yp[c * DIM + i],     w1[ i      * DIM + d], y0);
                y1 = fmaf(Yp[c * DIM + i + 1], w1[(i + 1) * DIM + d], y1);
            }
            Hs[c * DIM + d] = fmaxf(y0 + y1, 0.f);
        }
        __syncthreads();

        // ---- Y = H @ W2 + b2 ;  X += Y + Yproj ----
        {
            float y0 = lb2[d], y1 = 0.f;
            #pragma unroll
            for (int i = 0; i < DIM; i += 2) {
                y0 = fmaf(Hs[c * DIM + i],     w2[ i      * DIM + d], y0);
                y1 = fmaf(Hs[c * DIM + i + 1], w2[(i + 1) * DIM + d], y1);
            }
            // thread (c,d) is the sole reader+writer of Xs[c][d]: no hazard
            Xs[c * DIM + d] += (y0 + y1) + Yp[c * DIM + d];
        }
        __syncthreads();
    }

    // ---- Unembed: out[c][t] = X[c] . Wu[:,t] + bu[t] ----
    if (tid < CTX * NTOK) {                   // 65 threads
        const int cc = tid / NTOK;
        const int t  = tid % NTOK;
        float y0 = sbu[t], y1 = 0.f;
        #pragma unroll
        for (int i = 0; i < DIM; i += 2) {
            y0 = fmaf(Xs[cc * DIM + i],     sWu[ i      * NTOK + t], y0);
            y1 = fmaf(Xs[cc * DIM + i + 1], sWu[(i + 1) * NTOK + t], y1);
        }
        out[tid] = y0 + y1;
    }
}

extern "C" void kernel_launch(void* const* d_in, const int* in_sizes, int n_in,
                              void* d_out, int out_size) {
    (void)in_sizes; (void)n_in; (void)out_size;
    const int*   toks   = (const int*)  d_in[0];
    const float* pos    = (const float*)d_in[1];
    const float* tokemb = (const float*)d_in[2];
    const float* Wq     = (const float*)d_in[3];
    const float* Wk     = (const float*)d_in[4];
    const float* Wv     = (const float*)d_in[5];
    const float* Wp     = (const float*)d_in[6];
    const float* bp     = (const float*)d_in[7];
    const float* W1     = (const float*)d_in[8];
    const float* b1     = (const float*)d_in[9];
    const float* W2     = (const float*)d_in[10];
    const float* b2     = (const float*)d_in[11];
    const float* Wu     = (const float*)d_in[12];
    const float* bu     = (const float*)d_in[13];
    float* out = (float*)d_out;

    static bool attr_set = false;   // idempotent attribute set (not a work guard)
    if (!attr_set) {
        cudaFuncSetAttribute(transformer_fused_kernel,
                             cudaFuncAttributeMaxDynamicSharedMemorySize,
                             SMEM_BYTES);
        attr_set = true;
    }

    transformer_fused_kernel<<<1, 160, SMEM_BYTES>>>(
        toks, pos, tokemb, Wq, Wk, Wv, Wp, bp, W1, b1, W2, b2, Wu, bu, out);
}

// round 3
// speedup vs baseline: 1.2980x; 1.2980x over previous
#include <cuda_runtime.h>
#include <math_constants.h>

// Tiny transformer fully fused into ONE kernel, ONE block of 512 threads.
// CONTEXT=5, DIM=32, HEADS=4 (hd=8), NTOK=13, LAYERS=4.
//
// Warp-specialized register pipelining: threads are split into 3 groups of
// 160 (A=tid 0..159, B=160..319, C=320..479; warp 15 idle). Each group keeps
// two 32-float weight columns in REGISTERS:
//   A: Wq (QKV phase)  + W2 (mlp2/residual phase)
//   B: Wk (QKV)        + Wp (proj)   [repurposed to Wu for the epilogue]
//   C: Wv (QKV)        + W1 (mlp1)
// Next layer's weights are prefetched into the same registers immediately
// after their last use in the current layer, so the global-load latency
// overlaps the following ~5 phases of compute. Only layer 0's loads are
// exposed (once, at kernel entry).

#define CTX    5
#define DIM    32
#define NTOK   13
#define HEADS  4
#define HD     8
#define LAYERS 4

__global__ __launch_bounds__(512, 1)
void transformer_fused_kernel(
    const int*   __restrict__ toks,      // [5]
    const float* __restrict__ pos,       // [5,32]
    const float* __restrict__ tokemb,    // [13,32]
    const float* __restrict__ gWq,       // [4,32,32]
    const float* __restrict__ gWk,
    const float* __restrict__ gWv,
    const float* __restrict__ gWp,
    const float* __restrict__ gbp,       // [4,32]
    const float* __restrict__ gW1,
    const float* __restrict__ gb1,
    const float* __restrict__ gW2,
    const float* __restrict__ gb2,
    const float* __restrict__ gWu,       // [32,13]
    const float* __restrict__ gbu,       // [13]
    float*       __restrict__ out)       // [5,13]
{
    __shared__ float Xs[CTX * DIM];
    __shared__ float Qs[CTX * DIM];   // reused as Ycat after scores are read
    __shared__ float Ks[CTX * DIM];
    __shared__ float Vs[CTX * DIM];
    __shared__ float Yp[CTX * DIM];
    __shared__ float Hs[CTX * DIM];
    __shared__ float Ss[HEADS * CTX * CTX];

    const int  tid = threadIdx.x;
    const int  g   = tid / 160;           // 0,1,2 active; 3 = idle warp 15
    const int  r   = tid - g * 160;       // 0..159 within group
    const int  c   = r >> 5;              // context row (warp-uniform)
    const int  d   = r & 31;              // feature column (lane)
    const bool act = (g < 3);

    float wA[DIM];   // first-use weights  (Wq / Wk / Wv)
    float wB[DIM];   // second-use weights (W2 / Wp / W1), then Wu for B
    float lb = 0.f;  // bias paired with wB (b2 / bp / b1), then bu for B

    // ---- Layer-0 prefetch: all groups issue their 64 weight loads now ----
    if (act) {
        const float* WA0 = (g == 0) ? gWq : (g == 1) ? gWk : gWv;
        const float* WB0 = (g == 0) ? gW2 : (g == 1) ? gWp : gW1;
        #pragma unroll
        for (int i = 0; i < DIM; ++i) {
            wA[i] = WA0[i * DIM + d];
            wB[i] = WB0[i * DIM + d];
        }
        lb = ((g == 0) ? gb2 : (g == 1) ? gbp : gb1)[d];
    }
    // ---- Embedding (overlaps the weight prefetch above) ----
    if (tid < 160) Xs[r] = tokemb[toks[c] * DIM + d] + pos[r];
    __syncthreads();

    #pragma unroll 1
    for (int l = 0; l < LAYERS; ++l) {
        const int ln = (l < LAYERS - 1) ? l + 1 : l;   // next layer (clamped)

        // ---- QKV: A->Q, B->K, C->V, in parallel; then prefetch next wA ----
        if (act) {
            float y0 = 0.f, y1 = 0.f;
            #pragma unroll
            for (int i = 0; i < DIM; i += 2) {
                y0 = fmaf(Xs[c * DIM + i],     wA[i],     y0);
                y1 = fmaf(Xs[c * DIM + i + 1], wA[i + 1], y1);
            }
            const float y = y0 + y1;
            if (g == 0)      Qs[r] = y;
            else if (g == 1) Ks[r] = y;
            else             Vs[r] = y;

            const float* WAn = (g == 0) ? gWq : (g == 1) ? gWk : gWv;
            #pragma unroll
            for (int i = 0; i < DIM; ++i)
                wA[i] = WAn[ln * DIM * DIM + i * DIM + d];
        }
        __syncthreads();

        // ---- Scores: 100 threads, one per (h,q,k), causal only ----
        if (tid < HEADS * CTX * CTX) {
            const int h  = tid / (CTX * CTX);
            const int rr = tid % (CTX * CTX);
            const int qq = rr / CTX;
            const int kk = rr % CTX;
            if (kk <= qq) {
                float a0 = 0.f, a1 = 0.f;
                #pragma unroll
                for (int i = 0; i < HD; i += 2) {
                    a0 = fmaf(Qs[qq * DIM + h * HD + i],
                              Ks[kk * DIM + h * HD + i],     a0);
                    a1 = fmaf(Qs[qq * DIM + h * HD + i + 1],
                              Ks[kk * DIM + h * HD + i + 1], a1);
                }
                Ss[tid] = (a0 + a1) * 0.17677669529663687f;  // 1/sqrt(32)
            }
        }
        __syncthreads();

        // ---- Softmax: 20 threads, one per (h,q) row ----
        if (tid < HEADS * CTX) {
            const int h  = tid / CTX;
            const int qq = tid % CTX;
            float* row = Ss + (h * CTX + qq) * CTX;
            float m = -CUDART_INF_F;
            for (int kk = 0; kk <= qq; ++kk) m = fmaxf(m, row[kk]);
            float e[CTX];
            float s = 0.f;
            for (int kk = 0; kk <= qq; ++kk) {
                e[kk] = __expf(row[kk] - m);
                s += e[kk];
            }
            const float inv = 1.f / s;
            for (int kk = 0; kk <= qq; ++kk)      row[kk] = e[kk] * inv;
            for (int kk = qq + 1; kk < CTX; ++kk) row[kk] = 0.f;
        }
        __syncthreads();

        // ---- Ycat = S @ V (group A; reuse Qs) ----
        if (g == 0) {
            const int h = d >> 3;
            const float* srow = Ss + (h * CTX + c) * CTX;
            float y = 0.f;
            #pragma unroll
            for (int kk = 0; kk < CTX; ++kk)
                y = fmaf(srow[kk], Vs[kk * DIM + d], y);
            Qs[r] = y;
        }
        __syncthreads();

        // ---- Yproj = Ycat @ Wp + bp (group B, weights in regs) ----
        if (g == 1) {
            float y0 = lb, y1 = 0.f;
            #pragma unroll
            for (int i = 0; i < DIM; i += 2) {
                y0 = fmaf(Qs[c * DIM + i],     wB[i],     y0);
                y1 = fmaf(Qs[c * DIM + i + 1], wB[i + 1], y1);
            }
            Yp[r] = y0 + y1;
            // prefetch: next layer's Wp, or (final layer) the Wu epilogue cols
            if (l < LAYERS - 1) {
                #pragma unroll
                for (int i = 0; i < DIM; ++i)
                    wB[i] = gWp[ln * DIM * DIM + i * DIM + d];
                lb = gbp[ln * DIM + d];
            } else if (r < CTX * NTOK) {
                const int t = r % NTOK;
                #pragma unroll
                for (int i = 0; i < DIM; ++i)
                    wB[i] = gWu[i * NTOK + t];
                lb = gbu[t];
            }
        }
        __syncthreads();

        // ---- H = relu(Yproj @ W1 + b1) (group C) ----
        if (g == 2) {
            float y0 = lb, y1 = 0.f;
            #pragma unroll
            for (int i = 0; i < DIM; i += 2) {
                y0 = fmaf(Yp[c * DIM + i],     wB[i],     y0);
                y1 = fmaf(Yp[c * DIM + i + 1], wB[i + 1], y1);
            }
            Hs[r] = fmaxf(y0 + y1, 0.f);
            #pragma unroll
            for (int i = 0; i < DIM; ++i)
                wB[i] = gW1[ln * DIM * DIM + i * DIM + d];
            lb = gb1[ln * DIM + d];
        }
        __syncthreads();

        // ---- Y = H @ W2 + b2 ; X += Y + Yproj (group A) ----
        if (g == 0) {
            float y0 = lb, y1 = 0.f;
            #pragma unroll
            for (int i = 0; i < DIM; i += 2) {
                y0 = fmaf(Hs[c * DIM + i],     wB[i],     y0);
                y1 = fmaf(Hs[c * DIM + i + 1], wB[i + 1], y1);
            }
            // thread (c,d) is the sole reader+writer of Xs[r]: no hazard
            Xs[r] += (y0 + y1) + Yp[r];
            #pragma unroll
            for (int i = 0; i < DIM; ++i)
                wB[i] = gW2[ln * DIM * DIM + i * DIM + d];
            lb = gb2[ln * DIM + d];
        }
        __syncthreads();
    }

    // ---- Unembed (group B, Wu already in registers): out = X @ Wu + bu ----
    if (g == 1 && r < CTX * NTOK) {
        const int cc = r / NTOK;
        float y0 = lb, y1 = 0.f;
        #pragma unroll
        for (int i = 0; i < DIM; i += 2) {
            y0 = fmaf(Xs[cc * DIM + i],     wB[i],     y0);
            y1 = fmaf(Xs[cc * DIM + i + 1], wB[i + 1], y1);
        }
        out[r] = y0 + y1;
    }
}

extern "C" void kernel_launch(void* const* d_in, const int* in_sizes, int n_in,
                              void* d_out, int out_size) {
    (void)in_sizes; (void)n_in; (void)out_size;
    const int*   toks   = (const int*)  d_in[0];
    const float* pos    = (const float*)d_in[1];
    const float* tokemb = (const float*)d_in[2];
    const float* Wq     = (const float*)d_in[3];
    const float* Wk     = (const float*)d_in[4];
    const float* Wv     = (const float*)d_in[5];
    const float* Wp     = (const float*)d_in[6];
    const float* bp     = (const float*)d_in[7];
    const float* W1     = (const float*)d_in[8];
    const float* b1     = (const float*)d_in[9];
    const float* W2     = (const float*)d_in[10];
    const float* b2     = (const float*)d_in[11];
    const float* Wu     = (const float*)d_in[12];
    const float* bu     = (const float*)d_in[13];
    float* out = (float*)d_out;

    transformer_fused_kernel<<<1, 512>>>(toks, pos, tokemb, Wq, Wk, Wv, Wp, bp,
                                         W1, b1, W2, b2, Wu, bu, out);
}

// round 4
// speedup vs baseline: 1.6225x; 1.2500x over previous
#include <cuda_runtime.h>
#include <math_constants.h>

// Tiny transformer fully fused into ONE kernel, ONE block of 512 threads.
// CONTEXT=5, DIM=32, HEADS=4 (hd=8), NTOK=13, LAYERS=4.
//
// Groups of 160 threads (A=0..159, B=160..319, C=320..479; warp 15 idle)
// keep weight columns in REGISTERS, prefetching the next layer's weights
// right after last use (load latency overlaps ~5 phases of compute):
//   A: Wq + W2, B: Wk + Wp (then Wu), C: Wv + W1.
// Softmax has no max-subtraction (scores are tiny; exp(s)/sum(exp(s)) is
// exact): exp is computed in parallel by 100 lanes and the row-sum is a
// 3-step width-8 butterfly shuffle -> softmax costs ONE short phase.

#define CTX    5
#define DIM    32
#define NTOK   13
#define HEADS  4
#define HD     8
#define LAYERS 4
#define SCALE  0.17677669529663687f   // 1/sqrt(32)

__global__ __launch_bounds__(512, 1)
void transformer_fused_kernel(
    const int*   __restrict__ toks,
    const float* __restrict__ pos,
    const float* __restrict__ tokemb,
    const float* __restrict__ gWq,
    const float* __restrict__ gWk,
    const float* __restrict__ gWv,
    const float* __restrict__ gWp,
    const float* __restrict__ gbp,
    const float* __restrict__ gW1,
    const float* __restrict__ gb1,
    const float* __restrict__ gW2,
    const float* __restrict__ gb2,
    const float* __restrict__ gWu,
    const float* __restrict__ gbu,
    float*       __restrict__ out)
{
    __shared__ __align__(16) float Xs[CTX * DIM];
    __shared__ __align__(16) float Qs[CTX * DIM];   // becomes Ycat
    __shared__ __align__(16) float Ks[CTX * DIM];
    __shared__ __align__(16) float Vs[CTX * DIM];
    __shared__ __align__(16) float Yp[CTX * DIM];
    __shared__ __align__(16) float Hs[CTX * DIM];
    __shared__ __align__(16) float Ss[HEADS * CTX * 8];  // rows padded to 8

    const int  tid = threadIdx.x;
    const int  g   = tid / 160;          // 0,1,2 active; 3 = idle warp 15
    const int  r   = tid - g * 160;      // 0..159
    const int  c   = r >> 5;             // context row
    const int  d   = r & 31;             // feature column
    const bool act = (g < 3);

    float wA[DIM];   // Wq / Wk / Wv columns
    float wB[DIM];   // W2 / Wp / W1 columns (B gets Wu at the end)
    float lb = 0.f;  // b2 / bp / b1 (then bu)

    // ---- Layer-0 register prefetch (the only exposed weight latency) ----
    if (act) {
        const float* WA0 = (g == 0) ? gWq : (g == 1) ? gWk : gWv;
        const float* WB0 = (g == 0) ? gW2 : (g == 1) ? gWp : gW1;
        #pragma unroll
        for (int i = 0; i < DIM; ++i) {
            wA[i] = WA0[i * DIM + d];
            wB[i] = WB0[i * DIM + d];
        }
        lb = ((g == 0) ? gb2 : (g == 1) ? gbp : gb1)[d];
    }
    // ---- Embedding (overlaps prefetch) ----
    if (tid < 160) Xs[r] = tokemb[toks[c] * DIM + d] + pos[r];
    __syncthreads();

    #pragma unroll 1
    for (int l = 0; l < LAYERS; ++l) {
        const int ln = l + 1;

        // ================= QKV (A->Q, B->K, C->V in parallel) ============
        if (act) {
            const float4* xr = (const float4*)(Xs + c * DIM);
            float y0 = 0.f, y1 = 0.f, y2 = 0.f, y3 = 0.f;
            #pragma unroll
            for (int i = 0; i < 8; ++i) {
                const float4 x = xr[i];
                y0 = fmaf(x.x, wA[4 * i    ], y0);
                y1 = fmaf(x.y, wA[4 * i + 1], y1);
                y2 = fmaf(x.z, wA[4 * i + 2], y2);
                y3 = fmaf(x.w, wA[4 * i + 3], y3);
            }
            const float y = (y0 + y1) + (y2 + y3);
            if (g == 0)      Qs[r] = y;
            else if (g == 1) Ks[r] = y;
            else             Vs[r] = y;

            if (l < LAYERS - 1) {   // prefetch next layer's Wq/Wk/Wv
                const float* WAn = (g == 0) ? gWq : (g == 1) ? gWk : gWv;
                #pragma unroll
                for (int i = 0; i < DIM; ++i)
                    wA[i] = WAn[ln * DIM * DIM + i * DIM + d];
            }
        }
        __syncthreads();

        // ====== Scores + exp + rowsum + normalize, ONE phase =============
        // tid = (h*5+qq)*8 + kk ; kk in 0..7, rows of 8 lanes inside a warp
        if (tid < 160) {
            const int row = tid >> 3;        // 0..19 == h*5+qq
            const int kk  = tid & 7;
            const int h   = row / 5;
            const int qq  = row - h * 5;
            float e = 0.f;
            if (kk <= qq) {                  // causal; kk in 5..7 masked too
                const float4 q0 = *(const float4*)(Qs + qq * DIM + h * HD);
                const float4 q1 = *(const float4*)(Qs + qq * DIM + h * HD + 4);
                const float4 k0 = *(const float4*)(Ks + kk * DIM + h * HD);
                const float4 k1 = *(const float4*)(Ks + kk * DIM + h * HD + 4);
                float a0 = q0.x * k0.x + q0.z * k0.z;
                float a1 = q0.y * k0.y + q0.w * k0.w;
                a0 += q1.x * k1.x + q1.z * k1.z;
                a1 += q1.y * k1.y + q1.w * k1.w;
                e = __expf((a0 + a1) * SCALE);
            }
            float s = e;                      // width-8 butterfly row sum
            s += __shfl_xor_sync(0xFFFFFFFFu, s, 1, 8);
            s += __shfl_xor_sync(0xFFFFFFFFu, s, 2, 8);
            s += __shfl_xor_sync(0xFFFFFFFFu, s, 4, 8);
            if (kk < CTX)
                Ss[row * 8 + kk] = (kk <= qq) ? __fdividef(e, s) : 0.f;
        }
        __syncthreads();

        // ================= Ycat = S @ V (group A; reuse Qs) ==============
        if (g == 0) {
            const int h = d >> 3;
            const float* srow = Ss + (h * CTX + c) * 8;
            const float4 s03 = *(const float4*)srow;
            const float  s4  = srow[4];
            float y = s03.x * Vs[0 * DIM + d];
            y = fmaf(s03.y, Vs[1 * DIM + d], y);
            y = fmaf(s03.z, Vs[2 * DIM + d], y);
            y = fmaf(s03.w, Vs[3 * DIM + d], y);
            y = fmaf(s4,    Vs[4 * DIM + d], y);
            Qs[r] = y;
        }
        __syncthreads();

        // ================= Yproj = Ycat @ Wp + bp (group B) ==============
        if (g == 1) {
            const float4* xr = (const float4*)(Qs + c * DIM);
            float y0 = lb, y1 = 0.f, y2 = 0.f, y3 = 0.f;
            #pragma unroll
            for (int i = 0; i < 8; ++i) {
                const float4 x = xr[i];
                y0 = fmaf(x.x, wB[4 * i    ], y0);
                y1 = fmaf(x.y, wB[4 * i + 1], y1);
                y2 = fmaf(x.z, wB[4 * i + 2], y2);
                y3 = fmaf(x.w, wB[4 * i + 3], y3);
            }
            Yp[r] = (y0 + y1) + (y2 + y3);
            if (l < LAYERS - 1) {            // prefetch next Wp
                #pragma unroll
                for (int i = 0; i < DIM; ++i)
                    wB[i] = gWp[ln * DIM * DIM + i * DIM + d];
                lb = gbp[ln * DIM + d];
            } else if (r < CTX * NTOK) {     // prefetch Wu for epilogue
                const int t = r % NTOK;
                #pragma unroll
                for (int i = 0; i < DIM; ++i)
                    wB[i] = gWu[i * NTOK + t];
                lb = gbu[t];
            }
        }
        __syncthreads();

        // ================= H = relu(Yproj @ W1 + b1) (group C) ===========
        if (g == 2) {
            const float4* xr = (const float4*)(Yp + c * DIM);
            float y0 = lb, y1 = 0.f, y2 = 0.f, y3 = 0.f;
            #pragma unroll
            for (int i = 0; i < 8; ++i) {
                const float4 x = xr[i];
                y0 = fmaf(x.x, wB[4 * i    ], y0);
                y1 = fmaf(x.y, wB[4 * i + 1], y1);
                y2 = fmaf(x.z, wB[4 * i + 2], y2);
                y3 = fmaf(x.w, wB[4 * i + 3], y3);
            }
            Hs[r] = fmaxf((y0 + y1) + (y2 + y3), 0.f);
            if (l < LAYERS - 1) {            // prefetch next W1
                #pragma unroll
                for (int i = 0; i < DIM; ++i)
                    wB[i] = gW1[ln * DIM * DIM + i * DIM + d];
                lb = gb1[ln * DIM + d];
            }
        }
        __syncthreads();

        // ========== Y = H @ W2 + b2 ; X += Y + Yproj (group A) ===========
        if (g == 0) {
            const float4* xr = (const float4*)(Hs + c * DIM);
            float y0 = lb, y1 = 0.f, y2 = 0.f, y3 = 0.f;
            #pragma unroll
            for (int i = 0; i < 8; ++i) {
                const float4 x = xr[i];
                y0 = fmaf(x.x, wB[4 * i    ], y0);
                y1 = fmaf(x.y, wB[4 * i + 1], y1);
                y2 = fmaf(x.z, wB[4 * i + 2], y2);
                y3 = fmaf(x.w, wB[4 * i + 3], y3);
            }
            // thread (c,d) is the sole reader+writer of Xs[r]: no hazard
            Xs[r] += ((y0 + y1) + (y2 + y3)) + Yp[r];
            if (l < LAYERS - 1) {            // prefetch next W2
                #pragma unroll
                for (int i = 0; i < DIM; ++i)
                    wB[i] = gW2[ln * DIM * DIM + i * DIM + d];
                lb = gb2[ln * DIM + d];
            }
        }
        __syncthreads();
    }

    // ---- Unembed (group B, Wu in registers): out = X @ Wu + bu ----
    if (g == 1 && r < CTX * NTOK) {
        const int cc = r / NTOK;
        const float4* xr = (const float4*)(Xs + cc * DIM);
        float y0 = lb, y1 = 0.f, y2 = 0.f, y3 = 0.f;
        #pragma unroll
        for (int i = 0; i < 8; ++i) {
            const float4 x = xr[i];
            y0 = fmaf(x.x, wB[4 * i    ], y0);
            y1 = fmaf(x.y, wB[4 * i + 1], y1);
            y2 = fmaf(x.z, wB[4 * i + 2], y2);
            y3 = fmaf(x.w, wB[4 * i + 3], y3);
        }
        out[r] = (y0 + y1) + (y2 + y3);
    }
}

extern "C" void kernel_launch(void* const* d_in, const int* in_sizes, int n_in,
                              void* d_out, int out_size) {
    (void)in_sizes; (void)n_in; (void)out_size;
    const int*   toks   = (const int*)  d_in[0];
    const float* pos    = (const float*)d_in[1];
    const float* tokemb = (const float*)d_in[2];
    const float* Wq     = (const float*)d_in[3];
    const float* Wk     = (const float*)d_in[4];
    const float* Wv     = (const float*)d_in[5];
    const float* Wp     = (const float*)d_in[6];
    const float* bp     = (const float*)d_in[7];
    const float* W1     = (const float*)d_in[8];
    const float* b1     = (const float*)d_in[9];
    const float* W2     = (const float*)d_in[10];
    const float* b2     = (const float*)d_in[11];
    const float* Wu     = (const float*)d_in[12];
    const float* bu     = (const float*)d_in[13];
    float* out = (float*)d_out;

    transformer_fused_kernel<<<1, 512>>>(toks, pos, tokemb, Wq, Wk, Wv, Wp, bp,
                                         W1, b1, W2, b2, Wu, bu, out);
}

// round 5
// speedup vs baseline: 1.6857x; 1.0390x over previous
#include <cuda_runtime.h>
#include <math_constants.h>

// Tiny transformer fully fused into ONE kernel, ONE block of 480 threads.
// CONTEXT=5, DIM=32, HEADS=4 (hd=8), NTOK=13, LAYERS=4.
//
// 3 groups of 160 threads (5 warps each):
//   A (0..159):   Q matmul; scores+softmax+Ycat+Yproj phase.  regs: Wq + Wp
//   B (160..319): K and V matmuls; final unembed.             regs: Wk + Wv->Wu
//   C (320..479): H=relu(.@W1) and Y=.@W2 + residual.         regs: W1 + W2
// Next layer's weights are prefetched into registers right after last use,
// so global latency overlaps a full layer of compute.
//
// Only 3 barriers per layer: row-wise matmuls are chained INSIDE a warp via
// __shfl broadcasts (warp c's lanes hold row c), and softmax (5-wide, no
// max-subtract needed at these magnitudes) is recomputed inline per lane.

#define CTX    5
#define DIM    32
#define NTOK   13
#define HEADS  4
#define HD     8
#define LAYERS 4
#define SCALE  0.17677669529663687f   // 1/sqrt(32)
#define FULL   0xFFFFFFFFu

__global__ __launch_bounds__(480, 1)
void transformer_fused_kernel(
    const int*   __restrict__ toks,
    const float* __restrict__ pos,
    const float* __restrict__ tokemb,
    const float* __restrict__ gWq,
    const float* __restrict__ gWk,
    const float* __restrict__ gWv,
    const float* __restrict__ gWp,
    const float* __restrict__ gbp,
    const float* __restrict__ gW1,
    const float* __restrict__ gb1,
    const float* __restrict__ gW2,
    const float* __restrict__ gb2,
    const float* __restrict__ gWu,
    const float* __restrict__ gbu,
    float*       __restrict__ out)
{
    __shared__ __align__(16) float Xs [CTX * DIM];
    __shared__ __align__(16) float Qs [CTX * DIM];
    __shared__ __align__(16) float Ks [CTX * DIM];
    __shared__ __align__(16) float Vs [CTX * DIM];
    __shared__ __align__(16) float Yps[CTX * DIM];

    const int tid = threadIdx.x;
    const int g   = tid / 160;        // 0=A, 1=B, 2=C (warp-aligned groups)
    const int r   = tid - g * 160;    // 0..159
    const int c   = r >> 5;           // context row (warp-uniform)
    const int d   = r & 31;           // feature column (lane)

    float w0[DIM];    // A: Wq   B: Wk        C: W1
    float w1r[DIM];   // A: Wp   B: Wv -> Wu  C: W2
    float b0 = 0.f;   // A: bp   B: bu(end)   C: b1
    float b1v = 0.f;  //                      C: b2

    // ---- Layer-0 register prefetch (the only exposed weight latency) ----
    if (g == 0) {
        #pragma unroll
        for (int i = 0; i < DIM; ++i) {
            w0[i]  = gWq[i * DIM + d];
            w1r[i] = gWp[i * DIM + d];
        }
        b0 = gbp[d];
    } else if (g == 1) {
        #pragma unroll
        for (int i = 0; i < DIM; ++i) {
            w0[i]  = gWk[i * DIM + d];
            w1r[i] = gWv[i * DIM + d];
        }
    } else {
        #pragma unroll
        for (int i = 0; i < DIM; ++i) {
            w0[i]  = gW1[i * DIM + d];
            w1r[i] = gW2[i * DIM + d];
        }
        b0  = gb1[d];
        b1v = gb2[d];
    }
    // ---- Embedding (overlaps prefetch) ----
    if (tid < 160) Xs[r] = tokemb[toks[c] * DIM + d] + pos[r];
    __syncthreads();

    #pragma unroll 1
    for (int l = 0; l < LAYERS; ++l) {
        const int ln = l + 1;

        // ========== Phase 1: QKV (A -> Q ; B -> K and V) =================
        if (g == 0) {
            const float4* xr = (const float4*)(Xs + c * DIM);
            float a0 = 0.f, a1 = 0.f, a2 = 0.f, a3 = 0.f;
            #pragma unroll
            for (int i = 0; i < 8; ++i) {
                const float4 x = xr[i];
                a0 = fmaf(x.x, w0[4 * i    ], a0);
                a1 = fmaf(x.y, w0[4 * i + 1], a1);
                a2 = fmaf(x.z, w0[4 * i + 2], a2);
                a3 = fmaf(x.w, w0[4 * i + 3], a3);
            }
            Qs[r] = (a0 + a1) + (a2 + a3);
            if (l < LAYERS - 1) {
                #pragma unroll
                for (int i = 0; i < DIM; ++i)
                    w0[i] = gWq[ln * DIM * DIM + i * DIM + d];
            }
        } else if (g == 1) {
            const float4* xr = (const float4*)(Xs + c * DIM);
            float k0 = 0.f, k1 = 0.f, v0 = 0.f, v1 = 0.f;
            #pragma unroll
            for (int i = 0; i < 8; ++i) {
                const float4 x = xr[i];
                k0 = fmaf(x.x, w0[4 * i    ], k0);
                k1 = fmaf(x.y, w0[4 * i + 1], k1);
                k0 = fmaf(x.z, w0[4 * i + 2], k0);
                k1 = fmaf(x.w, w0[4 * i + 3], k1);
                v0 = fmaf(x.x, w1r[4 * i    ], v0);
                v1 = fmaf(x.y, w1r[4 * i + 1], v1);
                v0 = fmaf(x.z, w1r[4 * i + 2], v0);
                v1 = fmaf(x.w, w1r[4 * i + 3], v1);
            }
            Ks[r] = k0 + k1;
            Vs[r] = v0 + v1;
            if (l < LAYERS - 1) {
                #pragma unroll
                for (int i = 0; i < DIM; ++i) {
                    w0[i]  = gWk[ln * DIM * DIM + i * DIM + d];
                    w1r[i] = gWv[ln * DIM * DIM + i * DIM + d];
                }
            } else if (r < CTX * NTOK) {   // last layer: Wu + bu for epilogue
                const int t = r % NTOK;
                #pragma unroll
                for (int i = 0; i < DIM; ++i)
                    w1r[i] = gWu[i * NTOK + t];
                b0 = gbu[t];
            }
        }
        __syncthreads();

        // == Phase 2 (A): scores+softmax+Ycat inline, then Yproj via shfl ==
        if (g == 0) {
            const int h    = d >> 3;
            const int base = h * HD;
            const float4 qa = *(const float4*)(Qs + c * DIM + base);
            const float4 qb = *(const float4*)(Qs + c * DIM + base + 4);
            float e[CTX];
            #pragma unroll
            for (int k = 0; k < CTX; ++k) {
                if (k <= c) {
                    const float4 ka = *(const float4*)(Ks + k * DIM + base);
                    const float4 kb = *(const float4*)(Ks + k * DIM + base + 4);
                    float s0 = qa.x * ka.x + qa.z * ka.z;
                    float s1 = qa.y * ka.y + qa.w * ka.w;
                    s0 += qb.x * kb.x + qb.z * kb.z;
                    s1 += qb.y * kb.y + qb.w * kb.w;
                    e[k] = __expf((s0 + s1) * SCALE);
                } else {
                    e[k] = 0.f;
                }
            }
            const float inv = __fdividef(1.f, (e[0] + e[1]) + (e[2] + e[3]) + e[4]);
            float y = e[0] * Vs[0 * DIM + d];
            y = fmaf(e[1], Vs[1 * DIM + d], y);
            y = fmaf(e[2], Vs[2 * DIM + d], y);
            y = fmaf(e[3], Vs[3 * DIM + d], y);
            y = fmaf(e[4], Vs[4 * DIM + d], y);
            y *= inv;                                  // Ycat[c][d]

            // Yproj = Ycat @ Wp + bp  (warp-internal shuffle broadcast)
            float p0 = b0, p1 = 0.f, p2 = 0.f, p3 = 0.f;
            #pragma unroll
            for (int i = 0; i < DIM; i += 4) {
                p0 = fmaf(__shfl_sync(FULL, y, i    ), w1r[i    ], p0);
                p1 = fmaf(__shfl_sync(FULL, y, i + 1), w1r[i + 1], p1);
                p2 = fmaf(__shfl_sync(FULL, y, i + 2), w1r[i + 2], p2);
                p3 = fmaf(__shfl_sync(FULL, y, i + 3), w1r[i + 3], p3);
            }
            Yps[r] = (p0 + p1) + (p2 + p3);
            if (l < LAYERS - 1) {
                #pragma unroll
                for (int i = 0; i < DIM; ++i)
                    w1r[i] = gWp[ln * DIM * DIM + i * DIM + d];
                b0 = gbp[ln * DIM + d];
            }
        }
        __syncthreads();

        // == Phase 3 (C): H=relu(Yp@W1+b1); Y=H@W2+b2 via shfl; X update ==
        if (g == 2) {
            const float4* xr = (const float4*)(Yps + c * DIM);
            float a0 = b0, a1 = 0.f, a2 = 0.f, a3 = 0.f;
            #pragma unroll
            for (int i = 0; i < 8; ++i) {
                const float4 x = xr[i];
                a0 = fmaf(x.x, w0[4 * i    ], a0);
                a1 = fmaf(x.y, w0[4 * i + 1], a1);
                a2 = fmaf(x.z, w0[4 * i + 2], a2);
                a3 = fmaf(x.w, w0[4 * i + 3], a3);
            }
            const float hval = fmaxf((a0 + a1) + (a2 + a3), 0.f);

            float y0 = b1v, y1 = 0.f, y2 = 0.f, y3 = 0.f;
            #pragma unroll
            for (int i = 0; i < DIM; i += 4) {
                y0 = fmaf(__shfl_sync(FULL, hval, i    ), w1r[i    ], y0);
                y1 = fmaf(__shfl_sync(FULL, hval, i + 1), w1r[i + 1], y1);
                y2 = fmaf(__shfl_sync(FULL, hval, i + 2), w1r[i + 2], y2);
                y3 = fmaf(__shfl_sync(FULL, hval, i + 3), w1r[i + 3], y3);
            }
            // sole reader+writer of Xs[r] in this phase: no hazard
            Xs[r] += ((y0 + y1) + (y2 + y3)) + Yps[r];
            if (l < LAYERS - 1) {
                #pragma unroll
                for (int i = 0; i < DIM; ++i) {
                    w0[i]  = gW1[ln * DIM * DIM + i * DIM + d];
                    w1r[i] = gW2[ln * DIM * DIM + i * DIM + d];
                }
                b0  = gb1[ln * DIM + d];
                b1v = gb2[ln * DIM + d];
            }
        }
        __syncthreads();
    }

    // ---- Epilogue (B, Wu already in regs): out = X @ Wu + bu ----
    if (g == 1 && r < CTX * NTOK) {
        const int cc = r / NTOK;
        const float4* xr = (const float4*)(Xs + cc * DIM);
        float y0 = b0, y1 = 0.f, y2 = 0.f, y3 = 0.f;
        #pragma unroll
        for (int i = 0; i < 8; ++i) {
            const float4 x = xr[i];
            y0 = fmaf(x.x, w1r[4 * i    ], y0);
            y1 = fmaf(x.y, w1r[4 * i + 1], y1);
            y2 = fmaf(x.z, w1r[4 * i + 2], y2);
            y3 = fmaf(x.w, w1r[4 * i + 3], y3);
        }
        out[r] = (y0 + y1) + (y2 + y3);
    }
}

extern "C" void kernel_launch(void* const* d_in, const int* in_sizes, int n_in,
                              void* d_out, int out_size) {
    (void)in_sizes; (void)n_in; (void)out_size;
    const int*   toks   = (const int*)  d_in[0];
    const float* pos    = (const float*)d_in[1];
    const float* tokemb = (const float*)d_in[2];
    const float* Wq     = (const float*)d_in[3];
    const float* Wk     = (const float*)d_in[4];
    const float* Wv     = (const float*)d_in[5];
    const float* Wp     = (const float*)d_in[6];
    const float* bp     = (const float*)d_in[7];
    const float* W1     = (const float*)d_in[8];
    const float* b1     = (const float*)d_in[9];
    const float* W2     = (const float*)d_in[10];
    const float* b2     = (const float*)d_in[11];
    const float* Wu     = (const float*)d_in[12];
    const float* bu     = (const float*)d_in[13];
    float* out = (float*)d_out;

    transformer_fused_kernel<<<1, 480>>>(toks, pos, tokemb, Wq, Wk, Wv, Wp, bp,
                                         W1, b1, W2, b2, Wu, bu, out);
}